// round 1
// baseline (speedup 1.0000x reference)
#include <cuda_runtime.h>
#include <cuda_bf16.h>

// 3D Perlin noise, 8.39M points.
// perm table replicated 32x in shared (one copy per bank -> conflict-free
// random lookups), with perm[i]%12 packed into bits [16:20) of each entry.

__device__ __forceinline__ float fade_f(float t) {
    // 6t^5 - 15t^4 + 10t^3, same association as reference: ((t*t)*t)*(t*(t*6-15)+10)
    return t * t * t * (t * (t * 6.0f - 15.0f) + 10.0f);
}

__device__ __forceinline__ float lerp_f(float a, float b, float t) {
    return a + t * (b - a);
}

// grad3 dot, exact branchless equivalent of the 12-entry table:
//  h<4 : (+-x, +-y, 0), 4<=h<8 : (+-x, 0, +-z), h>=8 : (0, +-y, +-z)
//  sign of first comp  = -(h&1), sign of second = -(h&2)
__device__ __forceinline__ float gdot(int h, float x, float y, float z) {
    float u = (h < 8) ? x : y;
    float v = (h < 4) ? y : z;
    u = (h & 1) ? -u : u;
    v = (h & 2) ? -v : v;
    return u + v;
}

__device__ __forceinline__ float perlin_point(float x, float y, float z,
                                              const int* __restrict__ sp) {
    float fx = floorf(x), fy = floorf(y), fz = floorf(z);
    int xi = ((int)fx) & 255;
    int yi = ((int)fy) & 255;
    int zi = ((int)fz) & 255;
    float xf = x - fx, yf = y - fy, zf = z - fz;
    float u = fade_f(xf), v = fade_f(yf), w = fade_f(zf);

    // sp is pre-offset by lane; stride 32 ints => bank == lane, conflict-free.
    // Entries pack perm value (bits 0..7) and perm%12 (bits 16..19); the
    // (r + idx) & 255 chaining masks the high bits automatically.
#define P(i) sp[(((i) & 255) << 5)]
    int A  = P(xi);
    int B  = P(xi + 1);
    int AA = P(A + yi);
    int AB = P(A + yi + 1);
    int BA = P(B + yi);
    int BB = P(B + yi + 1);
    int aaa = P(AA + zi)     >> 16;
    int aab = P(AA + zi + 1) >> 16;
    int aba = P(AB + zi)     >> 16;
    int abb = P(AB + zi + 1) >> 16;
    int baa = P(BA + zi)     >> 16;
    int bab = P(BA + zi + 1) >> 16;
    int bba = P(BB + zi)     >> 16;
    int bbb = P(BB + zi + 1) >> 16;
#undef P

    float xm = xf - 1.0f, ym = yf - 1.0f, zm = zf - 1.0f;

    float g_aaa = gdot(aaa, xf, yf, zf);
    float g_aab = gdot(aab, xf, yf, zm);
    float g_aba = gdot(aba, xf, ym, zf);
    float g_abb = gdot(abb, xf, ym, zm);
    float g_baa = gdot(baa, xm, yf, zf);
    float g_bab = gdot(bab, xm, yf, zm);
    float g_bba = gdot(bba, xm, ym, zf);
    float g_bbb = gdot(bbb, xm, ym, zm);

    float x1 = lerp_f(g_aaa, g_baa, u);
    float x2 = lerp_f(g_aba, g_bba, u);
    float x3 = lerp_f(g_aab, g_bab, u);
    float x4 = lerp_f(g_abb, g_bbb, u);
    float y1 = lerp_f(x1, x2, v);
    float y2 = lerp_f(x3, x4, v);
    return lerp_f(y1, y2, w);
}

__global__ __launch_bounds__(256)
void PerlinNoise_kernel(const float4* __restrict__ xs,
                        const float4* __restrict__ ys,
                        const float4* __restrict__ zs,
                        const int* __restrict__ perm,
                        float4* __restrict__ out,
                        int n4) {
    __shared__ int s_perm[256 * 32];  // 32 KB, replicated per bank

    int t = threadIdx.x;
    int lane = t & 31;
    int warp = t >> 5;
    // 8 warps: each warp fills rows warp, warp+8, ... across its own lane column.
    #pragma unroll 4
    for (int i = warp; i < 256; i += 8) {
        int pv = __ldg(perm + i);                 // broadcast load
        s_perm[(i << 5) + lane] = pv | ((pv % 12) << 16);
    }
    __syncthreads();

    int idx = blockIdx.x * 256 + t;
    if (idx >= n4) return;

    const int* sp = s_perm + lane;

    float4 x4 = xs[idx];
    float4 y4 = ys[idx];
    float4 z4 = zs[idx];

    float4 o;
    o.x = perlin_point(x4.x, y4.x, z4.x, sp);
    o.y = perlin_point(x4.y, y4.y, z4.y, sp);
    o.z = perlin_point(x4.z, y4.z, z4.z, sp);
    o.w = perlin_point(x4.w, y4.w, z4.w, sp);

    out[idx] = o;
}

extern "C" void kernel_launch(void* const* d_in, const int* in_sizes, int n_in,
                              void* d_out, int out_size) {
    const float* x    = (const float*)d_in[0];
    const float* y    = (const float*)d_in[1];
    const float* z    = (const float*)d_in[2];
    const int*   perm = (const int*)d_in[3];
    // d_in[4] = grad3 (unused: gradient dot computed analytically, exact)

    int n  = in_sizes[0];
    int n4 = n >> 2;  // 32*512*512 is divisible by 4

    int blocks = (n4 + 255) / 256;
    PerlinNoise_kernel<<<blocks, 256>>>(
        (const float4*)x, (const float4*)y, (const float4*)z,
        perm, (float4*)d_out, n4);
}